// round 8
// baseline (speedup 1.0000x reference)
#include <cuda_runtime.h>
#include <cuda_bf16.h>
#include <math.h>
#include <stdint.h>

#define D_MODEL 1024
#define NHEAD   16
#define HDIM    64
#define BATCH   4
#define SEQ     2048
#define FFN_DIM 4096
#define ROWS    (BATCH * SEQ)   /* 8192 */

/* ================= PTX helpers (base sm_103 ISA only) ================= */
__device__ __forceinline__ uint32_t smem_u32(const void* p) {
    uint32_t a;
    asm("{ .reg .u64 t; cvta.to.shared.u64 t, %1; cvt.u32.u64 %0, t; }" : "=r"(a) : "l"(p));
    return a;
}
__device__ __forceinline__ void ldmx4(uint32_t* r, uint32_t addr) {
    asm volatile("ldmatrix.sync.aligned.m8n8.x4.shared.b16 {%0,%1,%2,%3}, [%4];"
                 : "=r"(r[0]), "=r"(r[1]), "=r"(r[2]), "=r"(r[3]) : "r"(addr));
}
__device__ __forceinline__ void mma16816(float* c, const uint32_t* a, const uint32_t* b) {
    asm volatile("mma.sync.aligned.m16n8k16.row.col.f32.bf16.bf16.f32 "
                 "{%0,%1,%2,%3}, {%4,%5,%6,%7}, {%8,%9}, {%0,%1,%2,%3};"
                 : "+f"(c[0]), "+f"(c[1]), "+f"(c[2]), "+f"(c[3])
                 : "r"(a[0]), "r"(a[1]), "r"(a[2]), "r"(a[3]), "r"(b[0]), "r"(b[1]));
}
__device__ __forceinline__ void cp_async16(uint32_t s, const void* g) {
    asm volatile("cp.async.cg.shared.global [%0], [%1], 16;" :: "r"(s), "l"(g) : "memory");
}
#define CP_COMMIT() asm volatile("cp.async.commit_group;" ::: "memory")
#define CP_WAIT0()  asm volatile("cp.async.wait_group 0;" ::: "memory")
#define CP_WAIT1()  asm volatile("cp.async.wait_group 1;" ::: "memory")

__device__ __forceinline__ void split_bf16(float v, __nv_bfloat16& h, __nv_bfloat16& l) {
    h = __float2bfloat16(v);
    l = __float2bfloat16(v - __bfloat162float(h));
}

/* ================= Scratch (__device__ globals) ================= */
__device__ float g_q   [ROWS * D_MODEL];
__device__ float g_k   [ROWS * D_MODEL];
__device__ float g_v   [ROWS * D_MODEL];
__device__ float g_x1  [ROWS * D_MODEL];

/* hi/lo-split activations (written by producers) */
__device__ __nv_bfloat16 g_xn_h  [ROWS * D_MODEL], g_xn_l  [ROWS * D_MODEL];
__device__ __nv_bfloat16 g_attn_h[ROWS * D_MODEL], g_attn_l[ROWS * D_MODEL];
__device__ __nv_bfloat16 g_h_h   [ROWS * FFN_DIM], g_h_l   [ROWS * FFN_DIM];

/* transposed + hi/lo-split weights: Wt[N,K] bf16 */
__device__ __nv_bfloat16 g_wq_h[D_MODEL * D_MODEL], g_wq_l[D_MODEL * D_MODEL];
__device__ __nv_bfloat16 g_wk_h[D_MODEL * D_MODEL], g_wk_l[D_MODEL * D_MODEL];
__device__ __nv_bfloat16 g_wv_h[D_MODEL * D_MODEL], g_wv_l[D_MODEL * D_MODEL];
__device__ __nv_bfloat16 g_wo_h[D_MODEL * D_MODEL], g_wo_l[D_MODEL * D_MODEL];
__device__ __nv_bfloat16 g_w1_h[D_MODEL * FFN_DIM], g_w1_l[D_MODEL * FFN_DIM];
__device__ __nv_bfloat16 g_w2_h[FFN_DIM * D_MODEL], g_w2_l[FFN_DIM * D_MODEL];

/* ================= weight transpose + bf16 hi/lo split ================= */
__global__ __launch_bounds__(256)
void wprep_kernel(const float* __restrict__ W, __nv_bfloat16* __restrict__ Th,
                  __nv_bfloat16* __restrict__ Tl, int K, int N)
{
    __shared__ float t[32][33];
    const int tx = threadIdx.x, ty = threadIdx.y;
    const int n0 = blockIdx.x * 32, k0 = blockIdx.y * 32;
#pragma unroll
    for (int i = ty; i < 32; i += 8)
        t[i][tx] = W[(size_t)(k0 + i) * N + n0 + tx];
    __syncthreads();
#pragma unroll
    for (int i = ty; i < 32; i += 8) {
        float x = t[tx][i];
        __nv_bfloat16 hi, lo; split_bf16(x, hi, lo);
        const size_t o = (size_t)(n0 + i) * K + k0 + tx;
        Th[o] = hi; Tl[o] = lo;
    }
}

/* ================= LayerNorm -> hi/lo bf16 ================= */
__global__ __launch_bounds__(256)
void ln_kernel(const float* __restrict__ x, const float* __restrict__ g,
               const float* __restrict__ be,
               __nv_bfloat16* __restrict__ oh, __nv_bfloat16* __restrict__ ol)
{
    __shared__ float sh[16];
    const int row = blockIdx.x;
    const int t   = threadIdx.x;
    const float4* xr = (const float4*)(x + (size_t)row * D_MODEL);
    float4 v = xr[t];
    float s  = v.x + v.y + v.z + v.w;
    float s2 = v.x*v.x + v.y*v.y + v.z*v.z + v.w*v.w;
#pragma unroll
    for (int o = 16; o > 0; o >>= 1) {
        s  += __shfl_xor_sync(0xffffffffu, s,  o);
        s2 += __shfl_xor_sync(0xffffffffu, s2, o);
    }
    if ((t & 31) == 0) { sh[t >> 5] = s; sh[8 + (t >> 5)] = s2; }
    __syncthreads();
    float ts = 0.f, ts2 = 0.f;
#pragma unroll
    for (int w = 0; w < 8; w++) { ts += sh[w]; ts2 += sh[8 + w]; }
    const float mean = ts * (1.0f / 1024.0f);
    const float var  = ts2 * (1.0f / 1024.0f) - mean * mean;
    const float inv  = rsqrtf(var + 1e-5f);
    float4 gg = ((const float4*)g)[t];
    float4 bb = ((const float4*)be)[t];
    float ox = (v.x - mean) * inv * gg.x + bb.x;
    float oy = (v.y - mean) * inv * gg.y + bb.y;
    float oz = (v.z - mean) * inv * gg.z + bb.z;
    float ow = (v.w - mean) * inv * gg.w + bb.w;
    __nv_bfloat16 hx, lx, hy, ly, hz, lz, hw, lw;
    split_bf16(ox, hx, lx); split_bf16(oy, hy, ly);
    split_bf16(oz, hz, lz); split_bf16(ow, hw, lw);
    const size_t o4 = (size_t)row * D_MODEL + (t << 2);
    *(__nv_bfloat162*)&oh[o4]     = __nv_bfloat162(hx, hy);
    *(__nv_bfloat162*)&oh[o4 + 2] = __nv_bfloat162(hz, hw);
    *(__nv_bfloat162*)&ol[o4]     = __nv_bfloat162(lx, ly);
    *(__nv_bfloat162*)&ol[o4 + 2] = __nv_bfloat162(lz, lw);
}

/* ================= HMMA GEMM, pre-split A and B =================
 * C[M,N] = (Ah+Al)[M,K] @ (Bh+Bl)[N,K]^T, 3-term bf16 mma, fp32 accum.
 * CTA 128x128, 8 warps of 64x32, K chunk 32, 3-stage cp.async pipeline.
 * Stage (32KB): Ah 8K | Al 8K | Bh 8K | Bl 8K, SW64 swizzle, 64B rows.
 * 96KB smem/CTA -> 2 CTAs/SM; __launch_bounds__(256,2) (<=128 regs).   */
#define G_STAGES     3
#define G_STAGE_B    32768u
#define G_SMEM_BYTES (G_STAGES * 32768)

__device__ __forceinline__ void g_load_stage(
    uint32_t sb, uint32_t sofs, int tid,
    const __nv_bfloat16* Ah, const __nv_bfloat16* Al,
    const __nv_bfloat16* Bh, const __nv_bfloat16* Bl, int K)
{
#pragma unroll
    for (int it = 0; it < 2; it++) {
        const int i = tid + it * 256;          /* 0..511 */
        const int r = i >> 2, c = i & 3;       /* 128 rows x 4 16B-chunks */
        const size_t go = (size_t)r * K + (c << 3);
        uint32_t off = (uint32_t)((r << 6) + (c << 4));
        uint32_t swo = off ^ ((off >> 3) & 0x30);
        cp_async16(sb + sofs + swo,          Ah + go);
        cp_async16(sb + sofs + 8192u + swo,  Al + go);
        cp_async16(sb + sofs + 16384u + swo, Bh + go);
        cp_async16(sb + sofs + 24576u + swo, Bl + go);
    }
}

template<bool QKV_STORE, bool RELU, bool RESID, bool SPLIT_OUT>
__global__ __launch_bounds__(256, 2)
void tgemm_kernel(const __nv_bfloat16* __restrict__ Ah,
                  const __nv_bfloat16* __restrict__ Al,
                  const __nv_bfloat16* __restrict__ Bh,
                  const __nv_bfloat16* __restrict__ Bl,
                  const float* __restrict__ bias, const float* __restrict__ resid,
                  float* __restrict__ C,
                  __nv_bfloat16* __restrict__ Ch, __nv_bfloat16* __restrict__ Cl,
                  int N, int K)
{
    extern __shared__ __align__(1024) char smc[];
    const uint32_t sb = smem_u32(smc);
    const int tid  = threadIdx.x;
    const int wid  = tid >> 5, lane = tid & 31;
    const int row0 = blockIdx.y << 7, col0 = blockIdx.x << 7;
    const int m0   = (wid >> 2) << 6;   /* warp M offset: 0 or 64  */
    const int n0   = (wid & 3) << 5;    /* warp N offset: 0..96    */

    float acc[4][4][4];
#pragma unroll
    for (int i = 0; i < 4; i++)
#pragma unroll
        for (int j = 0; j < 4; j++)
#pragma unroll
            for (int e = 0; e < 4; e++) acc[i][j][e] = 0.f;

    const int nc = K >> 5;                       /* K chunk = 32 */
    const __nv_bfloat16* Ab  = Ah + (size_t)row0 * K;
    const __nv_bfloat16* Alb = Al + (size_t)row0 * K;
    const __nv_bfloat16* Bb  = Bh + (size_t)col0 * K;
    const __nv_bfloat16* Blb = Bl + (size_t)col0 * K;

    /* prologue: stages 0, 1 */
    g_load_stage(sb, 0u, tid, Ab, Alb, Bb, Blb, K);
    CP_COMMIT();
    g_load_stage(sb, G_STAGE_B, tid, Ab + 32, Alb + 32, Bb + 32, Blb + 32, K);
    CP_COMMIT();

    /* ldmatrix lane mappings */
    const int qA  = lane >> 3, t8 = lane & 7;    /* A x4 */
    const int gB  = lane >> 3;                   /* B x4 (2 n8-frags) */
    const int jjB = gB >> 1, qbB = gB & 1;

    for (int ct = 0; ct < nc; ct++) {
        if (ct < nc - 1) { CP_WAIT1(); } else { CP_WAIT0(); }
        __syncthreads();
        if (ct + 2 < nc) {
            const int s = (ct + 2) % G_STAGES;
            const int ko = (ct + 2) << 5;
            g_load_stage(sb, (uint32_t)s * G_STAGE_B, tid,
                         Ab + ko, Alb + ko, Bb + ko, Blb + ko, K);
            CP_COMMIT();
        }
        const uint32_t bofs = (uint32_t)(ct % G_STAGES) * G_STAGE_B;

#pragma unroll
        for (int ks = 0; ks < 2; ks++) {
            const int k0 = ks << 4;
            uint32_t ah[4][4], al[4][4], bb2[4][2];
#pragma unroll
            for (int i = 0; i < 4; i++) {
                const int ml = m0 + (i << 4) + ((qA & 1) << 3) + t8;
                const int kl = k0 + ((qA >> 1) << 3);
                uint32_t off = (uint32_t)((ml << 6) + (kl << 1));
                uint32_t swo = off ^ ((off >> 3) & 0x30);
                ldmx4(ah[i], sb + bofs + swo);
                ldmx4(al[i], sb + bofs + 8192u + swo);
            }
            /* B-hi frags, consume, then overwrite with B-lo (halves live regs) */
#pragma unroll
            for (int jp = 0; jp < 2; jp++) {
                const int nl = n0 + (jp << 4) + (jjB << 3) + t8;
                const int kl = k0 + (qbB << 3);
                uint32_t off = (uint32_t)((nl << 6) + (kl << 1));
                uint32_t swo = off ^ ((off >> 3) & 0x30);
                uint32_t tmp[4];
                ldmx4(tmp, sb + bofs + 16384u + swo);
                bb2[jp * 2][0] = tmp[0]; bb2[jp * 2][1] = tmp[1];
                bb2[jp * 2 + 1][0] = tmp[2]; bb2[jp * 2 + 1][1] = tmp[3];
            }
#pragma unroll
            for (int i = 0; i < 4; i++)
#pragma unroll
                for (int j = 0; j < 4; j++) {
                    mma16816(acc[i][j], ah[i], bb2[j]);
                    mma16816(acc[i][j], al[i], bb2[j]);
                }
#pragma unroll
            for (int jp = 0; jp < 2; jp++) {
                const int nl = n0 + (jp << 4) + (jjB << 3) + t8;
                const int kl = k0 + (qbB << 3);
                uint32_t off = (uint32_t)((nl << 6) + (kl << 1));
                uint32_t swo = off ^ ((off >> 3) & 0x30);
                uint32_t tmp[4];
                ldmx4(tmp, sb + bofs + 24576u + swo);
                bb2[jp * 2][0] = tmp[0]; bb2[jp * 2][1] = tmp[1];
                bb2[jp * 2 + 1][0] = tmp[2]; bb2[jp * 2 + 1][1] = tmp[3];
            }
#pragma unroll
            for (int i = 0; i < 4; i++)
#pragma unroll
                for (int j = 0; j < 4; j++)
                    mma16816(acc[i][j], ah[i], bb2[j]);
        }
    }

    /* ---- epilogue: fused bias/resid/relu/permute/split ---- */
    const int rA  = lane >> 2;
    const int cp2 = (lane & 3) << 1;
#pragma unroll
    for (int i = 0; i < 4; i++) {
#pragma unroll
        for (int j = 0; j < 4; j++) {
            const int col = col0 + n0 + (j << 3) + cp2;
            const float b0 = bias[col], b1 = bias[col + 1];
#pragma unroll
            for (int h = 0; h < 2; h++) {
                const int row = row0 + m0 + (i << 4) + rA + (h << 3);
                float vx = acc[i][j][h * 2 + 0] + b0;
                float vy = acc[i][j][h * 2 + 1] + b1;
                if (RESID) {
                    const float2 rv = *(const float2*)&resid[(size_t)row * N + col];
                    vx += rv.x; vy += rv.y;
                }
                if (RELU) { vx = fmaxf(vx, 0.f); vy = fmaxf(vy, 0.f); }
                if (SPLIT_OUT) {
                    __nv_bfloat16 hx, lx, hy, ly;
                    split_bf16(vx, hx, lx); split_bf16(vy, hy, ly);
                    const size_t o = (size_t)row * N + col;
                    *(__nv_bfloat162*)&Ch[o] = __nv_bfloat162(hx, hy);
                    *(__nv_bfloat162*)&Cl[o] = __nv_bfloat162(lx, ly);
                } else if (QKV_STORE) {
                    const int b_ = row >> 11, l_ = row & (SEQ - 1);
                    const int h_ = col >> 6, hd_ = col & 63;
                    *(float2*)&C[(((size_t)(b_ * NHEAD + h_) * SEQ) + l_) * HDIM + hd_] =
                        make_float2(vx, vy);
                } else {
                    *(float2*)&C[(size_t)row * N + col] = make_float2(vx, vy);
                }
            }
        }
    }
}

/* ================= Flash attention (fp32 SIMT; split-bf16 output) ===== */
#define FL_SMEM_FLOATS (3 * 64 * 65 + 64 * 64)
#define FL_SMEM_BYTES  (FL_SMEM_FLOATS * 4)

__global__ __launch_bounds__(256)
void flash_kernel(const float* __restrict__ Qg, const float* __restrict__ Kg,
                  const float* __restrict__ Vg, const float* __restrict__ Bg,
                  __nv_bfloat16* __restrict__ Oh, __nv_bfloat16* __restrict__ Ol)
{
    extern __shared__ float fsm[];
    float (*Qs)[65] = (float(*)[65]) fsm;
    float (*Ks)[65] = (float(*)[65])(fsm + 64 * 65);
    float (*Ps)[65] = (float(*)[65])(fsm + 2 * 64 * 65);
    float (*Vs)[64] = (float(*)[64])(fsm + 3 * 64 * 65);

    const int tid = threadIdx.x;
    const int tx  = tid & 15, ty = tid >> 4;
    const int bh  = blockIdx.y;
    const int h   = bh & (NHEAD - 1);
    const int b   = bh >> 4;
    const int qt  = gridDim.x - 1 - blockIdx.x;
    const int q0  = qt << 6;

    const float* Qp = Qg + ((size_t)bh * SEQ + q0) * HDIM;
    const float* Kp = Kg + (size_t)bh * SEQ * HDIM;
    const float* Vp = Vg + (size_t)bh * SEQ * HDIM;
    const float* Bp = Bg + (size_t)h * SEQ * SEQ;

    for (int i = tid; i < 1024; i += 256) {
        const int r = i >> 4, s = (i & 15) << 2;
        float4 qv = *(const float4*)(Qp + r * HDIM + s);
        Qs[r][s] = qv.x; Qs[r][s + 1] = qv.y; Qs[r][s + 2] = qv.z; Qs[r][s + 3] = qv.w;
    }

    float m_i[4], l_i[4], oacc[4][4];
#pragma unroll
    for (int i = 0; i < 4; i++) {
        m_i[i] = -1e30f; l_i[i] = 0.f;
#pragma unroll
        for (int j = 0; j < 4; j++) oacc[i][j] = 0.f;
    }

    const float scale = 0.125f;
    const int ntiles = qt + 1;

    for (int kt = 0; kt < ntiles; kt++) {
        const int k0 = kt << 6;
        __syncthreads();
        for (int i = tid; i < 1024; i += 256) {
            const int r = i >> 4, s = (i & 15) << 2;
            float4 kv = *(const float4*)(Kp + (size_t)(k0 + r) * HDIM + s);
            Ks[r][s] = kv.x; Ks[r][s + 1] = kv.y; Ks[r][s + 2] = kv.z; Ks[r][s + 3] = kv.w;
            float4 vv = *(const float4*)(Vp + (size_t)(k0 + r) * HDIM + s);
            *(float4*)&Vs[r][s] = vv;
        }
        __syncthreads();

        float sv[4][4];
#pragma unroll
        for (int i = 0; i < 4; i++)
#pragma unroll
            for (int j = 0; j < 4; j++) sv[i][j] = 0.f;
#pragma unroll 8
        for (int d = 0; d < 64; d++) {
            float qf[4], kf[4];
#pragma unroll
            for (int i = 0; i < 4; i++) qf[i] = Qs[(ty << 2) + i][d];
#pragma unroll
            for (int j = 0; j < 4; j++) kf[j] = Ks[(tx << 2) + j][d];
#pragma unroll
            for (int i = 0; i < 4; i++)
#pragma unroll
                for (int j = 0; j < 4; j++)
                    sv[i][j] = fmaf(qf[i], kf[j], sv[i][j]);
        }

#pragma unroll
        for (int i = 0; i < 4; i++) {
            const int qi = q0 + (ty << 2) + i;
            float4 bvv = *(const float4*)(Bp + (size_t)qi * SEQ + k0 + (tx << 2));
            float bb[4] = {bvv.x, bvv.y, bvv.z, bvv.w};
#pragma unroll
            for (int j = 0; j < 4; j++) {
                const int kj = k0 + (tx << 2) + j;
                sv[i][j] = (kj <= qi) ? fmaf(sv[i][j], scale, bb[j]) : -1e30f;
            }
        }

#pragma unroll
        for (int i = 0; i < 4; i++) {
            float rmax = fmaxf(fmaxf(sv[i][0], sv[i][1]), fmaxf(sv[i][2], sv[i][3]));
#pragma unroll
            for (int o = 8; o > 0; o >>= 1)
                rmax = fmaxf(rmax, __shfl_xor_sync(0xffffffffu, rmax, o, 16));
            const float mnew = fmaxf(m_i[i], rmax);
            const float corr = __expf(m_i[i] - mnew);
            float rsum = 0.f;
#pragma unroll
            for (int j = 0; j < 4; j++) {
                sv[i][j] = __expf(sv[i][j] - mnew);
                rsum += sv[i][j];
            }
#pragma unroll
            for (int o = 8; o > 0; o >>= 1)
                rsum += __shfl_xor_sync(0xffffffffu, rsum, o, 16);
            l_i[i] = l_i[i] * corr + rsum;
            m_i[i] = mnew;
#pragma unroll
            for (int j = 0; j < 4; j++) oacc[i][j] *= corr;
#pragma unroll
            for (int j = 0; j < 4; j++)
                Ps[(ty << 2) + i][(tx << 2) + j] = sv[i][j];
        }
        __syncthreads();

#pragma unroll 8
        for (int c = 0; c < 64; c++) {
            float pf[4];
#pragma unroll
            for (int i = 0; i < 4; i++) pf[i] = Ps[(ty << 2) + i][c];
            float4 vf = *(const float4*)&Vs[c][tx << 2];
#pragma unroll
            for (int i = 0; i < 4; i++) {
                oacc[i][0] = fmaf(pf[i], vf.x, oacc[i][0]);
                oacc[i][1] = fmaf(pf[i], vf.y, oacc[i][1]);
                oacc[i][2] = fmaf(pf[i], vf.z, oacc[i][2]);
                oacc[i][3] = fmaf(pf[i], vf.w, oacc[i][3]);
            }
        }
    }

#pragma unroll
    for (int i = 0; i < 4; i++) {
        const int qi = q0 + (ty << 2) + i;
        const float inv = 1.0f / l_i[i];
        float o0 = oacc[i][0] * inv, o1 = oacc[i][1] * inv;
        float o2 = oacc[i][2] * inv, o3 = oacc[i][3] * inv;
        __nv_bfloat16 h0, l0, h1, l1, h2, l2, h3, l3;
        split_bf16(o0, h0, l0); split_bf16(o1, h1, l1);
        split_bf16(o2, h2, l2); split_bf16(o3, h3, l3);
        const size_t o = ((size_t)b * SEQ + qi) * D_MODEL + h * HDIM + (tx << 2);
        *(__nv_bfloat162*)&Oh[o]     = __nv_bfloat162(h0, h1);
        *(__nv_bfloat162*)&Oh[o + 2] = __nv_bfloat162(h2, h3);
        *(__nv_bfloat162*)&Ol[o]     = __nv_bfloat162(l0, l1);
        *(__nv_bfloat162*)&Ol[o + 2] = __nv_bfloat162(l2, l3);
    }
}

/* ================= Host launcher ================= */
extern "C" void kernel_launch(void* const* d_in, const int* in_sizes, int n_in,
                              void* d_out, int out_size)
{
    (void)in_sizes; (void)n_in; (void)out_size;
    const float* x    = (const float*)d_in[0];
    const float* relb = (const float*)d_in[1];
    const float* wq   = (const float*)d_in[2];
    const float* bq   = (const float*)d_in[3];
    const float* wk   = (const float*)d_in[4];
    const float* bk   = (const float*)d_in[5];
    const float* wv   = (const float*)d_in[6];
    const float* bv   = (const float*)d_in[7];
    const float* wo   = (const float*)d_in[8];
    const float* bo   = (const float*)d_in[9];
    const float* g1   = (const float*)d_in[10];
    const float* be1  = (const float*)d_in[11];
    const float* g2   = (const float*)d_in[12];
    const float* be2  = (const float*)d_in[13];
    const float* w1   = (const float*)d_in[14];
    const float* bf1  = (const float*)d_in[15];
    const float* w2   = (const float*)d_in[16];
    const float* bf2  = (const float*)d_in[17];
    float* out = (float*)d_out;

    float *q, *k, *v, *x1;
    cudaGetSymbolAddress((void**)&q,  g_q);
    cudaGetSymbolAddress((void**)&k,  g_k);
    cudaGetSymbolAddress((void**)&v,  g_v);
    cudaGetSymbolAddress((void**)&x1, g_x1);

    __nv_bfloat16 *xnh, *xnl, *ath, *atl, *hh, *hl;
    cudaGetSymbolAddress((void**)&xnh, g_xn_h);   cudaGetSymbolAddress((void**)&xnl, g_xn_l);
    cudaGetSymbolAddress((void**)&ath, g_attn_h); cudaGetSymbolAddress((void**)&atl, g_attn_l);
    cudaGetSymbolAddress((void**)&hh,  g_h_h);    cudaGetSymbolAddress((void**)&hl,  g_h_l);

    __nv_bfloat16 *wqh, *wql, *wkh, *wkl, *wvh, *wvl, *woh, *wol, *w1h, *w1l, *w2h, *w2l;
    cudaGetSymbolAddress((void**)&wqh, g_wq_h); cudaGetSymbolAddress((void**)&wql, g_wq_l);
    cudaGetSymbolAddress((void**)&wkh, g_wk_h); cudaGetSymbolAddress((void**)&wkl, g_wk_l);
    cudaGetSymbolAddress((void**)&wvh, g_wv_h); cudaGetSymbolAddress((void**)&wvl, g_wv_l);
    cudaGetSymbolAddress((void**)&woh, g_wo_h); cudaGetSymbolAddress((void**)&wol, g_wo_l);
    cudaGetSymbolAddress((void**)&w1h, g_w1_h); cudaGetSymbolAddress((void**)&w1l, g_w1_l);
    cudaGetSymbolAddress((void**)&w2h, g_w2_h); cudaGetSymbolAddress((void**)&w2l, g_w2_l);

    cudaFuncSetAttribute(flash_kernel,
                         cudaFuncAttributeMaxDynamicSharedMemorySize, FL_SMEM_BYTES);
    cudaFuncSetAttribute(tgemm_kernel<true,  false, false, false>,
                         cudaFuncAttributeMaxDynamicSharedMemorySize, G_SMEM_BYTES);
    cudaFuncSetAttribute(tgemm_kernel<false, false, true,  false>,
                         cudaFuncAttributeMaxDynamicSharedMemorySize, G_SMEM_BYTES);
    cudaFuncSetAttribute(tgemm_kernel<false, true,  false, true>,
                         cudaFuncAttributeMaxDynamicSharedMemorySize, G_SMEM_BYTES);

    /* weight prep: transpose [K,N] -> [N,K] + bf16 hi/lo split */
    const dim3 wb(32, 8);
    wprep_kernel<<<dim3(D_MODEL / 32, D_MODEL / 32), wb>>>(wq, wqh, wql, D_MODEL, D_MODEL);
    wprep_kernel<<<dim3(D_MODEL / 32, D_MODEL / 32), wb>>>(wk, wkh, wkl, D_MODEL, D_MODEL);
    wprep_kernel<<<dim3(D_MODEL / 32, D_MODEL / 32), wb>>>(wv, wvh, wvl, D_MODEL, D_MODEL);
    wprep_kernel<<<dim3(D_MODEL / 32, D_MODEL / 32), wb>>>(wo, woh, wol, D_MODEL, D_MODEL);
    wprep_kernel<<<dim3(FFN_DIM / 32, D_MODEL / 32), wb>>>(w1, w1h, w1l, D_MODEL, FFN_DIM);
    wprep_kernel<<<dim3(D_MODEL / 32, FFN_DIM / 32), wb>>>(w2, w2h, w2l, FFN_DIM, D_MODEL);

    const dim3 gd1024(D_MODEL / 128, ROWS / 128);  /* (8, 64)  */
    const dim3 gd4096(FFN_DIM / 128, ROWS / 128);  /* (32, 64) */

    ln_kernel<<<ROWS, 256>>>(x, g1, be1, xnh, xnl);
    tgemm_kernel<true,  false, false, false><<<gd1024, 256, G_SMEM_BYTES>>>(
        xnh, xnl, wqh, wql, bq, nullptr, q, nullptr, nullptr, D_MODEL, D_MODEL);
    tgemm_kernel<true,  false, false, false><<<gd1024, 256, G_SMEM_BYTES>>>(
        xnh, xnl, wkh, wkl, bk, nullptr, k, nullptr, nullptr, D_MODEL, D_MODEL);
    tgemm_kernel<true,  false, false, false><<<gd1024, 256, G_SMEM_BYTES>>>(
        xnh, xnl, wvh, wvl, bv, nullptr, v, nullptr, nullptr, D_MODEL, D_MODEL);
    flash_kernel<<<dim3(SEQ / 64, BATCH * NHEAD), 256, FL_SMEM_BYTES>>>(q, k, v, relb, ath, atl);
    tgemm_kernel<false, false, true,  false><<<gd1024, 256, G_SMEM_BYTES>>>(
        ath, atl, woh, wol, bo, x, x1, nullptr, nullptr, D_MODEL, D_MODEL);
    ln_kernel<<<ROWS, 256>>>(x1, g2, be2, xnh, xnl);
    tgemm_kernel<false, true,  false, true ><<<gd4096, 256, G_SMEM_BYTES>>>(
        xnh, xnl, w1h, w1l, bf1, nullptr, nullptr, hh, hl, FFN_DIM, D_MODEL);
    tgemm_kernel<false, false, true,  false><<<gd1024, 256, G_SMEM_BYTES>>>(
        hh, hl, w2h, w2l, bf2, x1, out, nullptr, nullptr, D_MODEL, FFN_DIM);
}

// round 9
// speedup vs baseline: 1.0103x; 1.0103x over previous
#include <cuda_runtime.h>
#include <cuda_bf16.h>
#include <math.h>
#include <stdint.h>

#define D_MODEL 1024
#define NHEAD   16
#define HDIM    64
#define BATCH   4
#define SEQ     2048
#define FFN_DIM 4096
#define ROWS    (BATCH * SEQ)   /* 8192 */

/* ================= PTX helpers (base sm_103 ISA only) ================= */
__device__ __forceinline__ uint32_t smem_u32(const void* p) {
    uint32_t a;
    asm("{ .reg .u64 t; cvta.to.shared.u64 t, %1; cvt.u32.u64 %0, t; }" : "=r"(a) : "l"(p));
    return a;
}
__device__ __forceinline__ void ldmx4(uint32_t* r, uint32_t addr) {
    asm volatile("ldmatrix.sync.aligned.m8n8.x4.shared.b16 {%0,%1,%2,%3}, [%4];"
                 : "=r"(r[0]), "=r"(r[1]), "=r"(r[2]), "=r"(r[3]) : "r"(addr));
}
__device__ __forceinline__ void mma16816(float* c, const uint32_t* a, const uint32_t* b) {
    asm volatile("mma.sync.aligned.m16n8k16.row.col.f32.bf16.bf16.f32 "
                 "{%0,%1,%2,%3}, {%4,%5,%6,%7}, {%8,%9}, {%0,%1,%2,%3};"
                 : "+f"(c[0]), "+f"(c[1]), "+f"(c[2]), "+f"(c[3])
                 : "r"(a[0]), "r"(a[1]), "r"(a[2]), "r"(a[3]), "r"(b[0]), "r"(b[1]));
}
__device__ __forceinline__ void cp_async16(uint32_t s, const void* g) {
    asm volatile("cp.async.cg.shared.global [%0], [%1], 16;" :: "r"(s), "l"(g) : "memory");
}
#define CP_COMMIT() asm volatile("cp.async.commit_group;" ::: "memory")
#define CP_WAIT0()  asm volatile("cp.async.wait_group 0;" ::: "memory")
#define CP_WAIT1()  asm volatile("cp.async.wait_group 1;" ::: "memory")

__device__ __forceinline__ void split_bf16(float v, __nv_bfloat16& h, __nv_bfloat16& l) {
    h = __float2bfloat16(v);
    l = __float2bfloat16(v - __bfloat162float(h));
}

/* ================= Scratch (__device__ globals) ================= */
__device__ float g_q   [ROWS * D_MODEL];
__device__ float g_k   [ROWS * D_MODEL];
__device__ float g_v   [ROWS * D_MODEL];
__device__ float g_x1  [ROWS * D_MODEL];

/* hi/lo-split activations (written by producers) */
__device__ __nv_bfloat16 g_xn_h  [ROWS * D_MODEL], g_xn_l  [ROWS * D_MODEL];
__device__ __nv_bfloat16 g_attn_h[ROWS * D_MODEL], g_attn_l[ROWS * D_MODEL];
__device__ __nv_bfloat16 g_h_h   [ROWS * FFN_DIM], g_h_l   [ROWS * FFN_DIM];

/* transposed + hi/lo-split weights: Wt[N,K] bf16 */
__device__ __nv_bfloat16 g_wq_h[D_MODEL * D_MODEL], g_wq_l[D_MODEL * D_MODEL];
__device__ __nv_bfloat16 g_wk_h[D_MODEL * D_MODEL], g_wk_l[D_MODEL * D_MODEL];
__device__ __nv_bfloat16 g_wv_h[D_MODEL * D_MODEL], g_wv_l[D_MODEL * D_MODEL];
__device__ __nv_bfloat16 g_wo_h[D_MODEL * D_MODEL], g_wo_l[D_MODEL * D_MODEL];
__device__ __nv_bfloat16 g_w1_h[D_MODEL * FFN_DIM], g_w1_l[D_MODEL * FFN_DIM];
__device__ __nv_bfloat16 g_w2_h[FFN_DIM * D_MODEL], g_w2_l[FFN_DIM * D_MODEL];

/* ================= weight transpose + bf16 hi/lo split ================= */
__global__ __launch_bounds__(256)
void wprep_kernel(const float* __restrict__ W, __nv_bfloat16* __restrict__ Th,
                  __nv_bfloat16* __restrict__ Tl, int K, int N)
{
    __shared__ float t[32][33];
    const int tx = threadIdx.x, ty = threadIdx.y;
    const int n0 = blockIdx.x * 32, k0 = blockIdx.y * 32;
#pragma unroll
    for (int i = ty; i < 32; i += 8)
        t[i][tx] = W[(size_t)(k0 + i) * N + n0 + tx];
    __syncthreads();
#pragma unroll
    for (int i = ty; i < 32; i += 8) {
        float x = t[tx][i];
        __nv_bfloat16 hi, lo; split_bf16(x, hi, lo);
        const size_t o = (size_t)(n0 + i) * K + k0 + tx;
        Th[o] = hi; Tl[o] = lo;
    }
}

/* ================= LayerNorm -> hi/lo bf16 ================= */
__global__ __launch_bounds__(256)
void ln_kernel(const float* __restrict__ x, const float* __restrict__ g,
               const float* __restrict__ be,
               __nv_bfloat16* __restrict__ oh, __nv_bfloat16* __restrict__ ol)
{
    __shared__ float sh[16];
    const int row = blockIdx.x;
    const int t   = threadIdx.x;
    const float4* xr = (const float4*)(x + (size_t)row * D_MODEL);
    float4 v = xr[t];
    float s  = v.x + v.y + v.z + v.w;
    float s2 = v.x*v.x + v.y*v.y + v.z*v.z + v.w*v.w;
#pragma unroll
    for (int o = 16; o > 0; o >>= 1) {
        s  += __shfl_xor_sync(0xffffffffu, s,  o);
        s2 += __shfl_xor_sync(0xffffffffu, s2, o);
    }
    if ((t & 31) == 0) { sh[t >> 5] = s; sh[8 + (t >> 5)] = s2; }
    __syncthreads();
    float ts = 0.f, ts2 = 0.f;
#pragma unroll
    for (int w = 0; w < 8; w++) { ts += sh[w]; ts2 += sh[8 + w]; }
    const float mean = ts * (1.0f / 1024.0f);
    const float var  = ts2 * (1.0f / 1024.0f) - mean * mean;
    const float inv  = rsqrtf(var + 1e-5f);
    float4 gg = ((const float4*)g)[t];
    float4 bb = ((const float4*)be)[t];
    float ox = (v.x - mean) * inv * gg.x + bb.x;
    float oy = (v.y - mean) * inv * gg.y + bb.y;
    float oz = (v.z - mean) * inv * gg.z + bb.z;
    float ow = (v.w - mean) * inv * gg.w + bb.w;
    __nv_bfloat16 hx, lx, hy, ly, hz, lz, hw, lw;
    split_bf16(ox, hx, lx); split_bf16(oy, hy, ly);
    split_bf16(oz, hz, lz); split_bf16(ow, hw, lw);
    const size_t o4 = (size_t)row * D_MODEL + (t << 2);
    *(__nv_bfloat162*)&oh[o4]     = __nv_bfloat162(hx, hy);
    *(__nv_bfloat162*)&oh[o4 + 2] = __nv_bfloat162(hz, hw);
    *(__nv_bfloat162*)&ol[o4]     = __nv_bfloat162(lx, ly);
    *(__nv_bfloat162*)&ol[o4 + 2] = __nv_bfloat162(lz, lw);
}

/* ================= HMMA GEMM (unchanged from round 8) ================= */
#define G_STAGES     3
#define G_STAGE_B    32768u
#define G_SMEM_BYTES (G_STAGES * 32768)

__device__ __forceinline__ void g_load_stage(
    uint32_t sb, uint32_t sofs, int tid,
    const __nv_bfloat16* Ah, const __nv_bfloat16* Al,
    const __nv_bfloat16* Bh, const __nv_bfloat16* Bl, int K)
{
#pragma unroll
    for (int it = 0; it < 2; it++) {
        const int i = tid + it * 256;          /* 0..511 */
        const int r = i >> 2, c = i & 3;       /* 128 rows x 4 16B-chunks */
        const size_t go = (size_t)r * K + (c << 3);
        uint32_t off = (uint32_t)((r << 6) + (c << 4));
        uint32_t swo = off ^ ((off >> 3) & 0x30);
        cp_async16(sb + sofs + swo,          Ah + go);
        cp_async16(sb + sofs + 8192u + swo,  Al + go);
        cp_async16(sb + sofs + 16384u + swo, Bh + go);
        cp_async16(sb + sofs + 24576u + swo, Bl + go);
    }
}

template<bool QKV_STORE, bool RELU, bool RESID, bool SPLIT_OUT>
__global__ __launch_bounds__(256, 2)
void tgemm_kernel(const __nv_bfloat16* __restrict__ Ah,
                  const __nv_bfloat16* __restrict__ Al,
                  const __nv_bfloat16* __restrict__ Bh,
                  const __nv_bfloat16* __restrict__ Bl,
                  const float* __restrict__ bias, const float* __restrict__ resid,
                  float* __restrict__ C,
                  __nv_bfloat16* __restrict__ Ch, __nv_bfloat16* __restrict__ Cl,
                  int N, int K)
{
    extern __shared__ __align__(1024) char smc[];
    const uint32_t sb = smem_u32(smc);
    const int tid  = threadIdx.x;
    const int wid  = tid >> 5, lane = tid & 31;
    const int row0 = blockIdx.y << 7, col0 = blockIdx.x << 7;
    const int m0   = (wid >> 2) << 6;
    const int n0   = (wid & 3) << 5;

    float acc[4][4][4];
#pragma unroll
    for (int i = 0; i < 4; i++)
#pragma unroll
        for (int j = 0; j < 4; j++)
#pragma unroll
            for (int e = 0; e < 4; e++) acc[i][j][e] = 0.f;

    const int nc = K >> 5;
    const __nv_bfloat16* Ab  = Ah + (size_t)row0 * K;
    const __nv_bfloat16* Alb = Al + (size_t)row0 * K;
    const __nv_bfloat16* Bb  = Bh + (size_t)col0 * K;
    const __nv_bfloat16* Blb = Bl + (size_t)col0 * K;

    g_load_stage(sb, 0u, tid, Ab, Alb, Bb, Blb, K);
    CP_COMMIT();
    g_load_stage(sb, G_STAGE_B, tid, Ab + 32, Alb + 32, Bb + 32, Blb + 32, K);
    CP_COMMIT();

    const int qA  = lane >> 3, t8 = lane & 7;
    const int gB  = lane >> 3;
    const int jjB = gB >> 1, qbB = gB & 1;

    for (int ct = 0; ct < nc; ct++) {
        if (ct < nc - 1) { CP_WAIT1(); } else { CP_WAIT0(); }
        __syncthreads();
        if (ct + 2 < nc) {
            const int s = (ct + 2) % G_STAGES;
            const int ko = (ct + 2) << 5;
            g_load_stage(sb, (uint32_t)s * G_STAGE_B, tid,
                         Ab + ko, Alb + ko, Bb + ko, Blb + ko, K);
            CP_COMMIT();
        }
        const uint32_t bofs = (uint32_t)(ct % G_STAGES) * G_STAGE_B;

#pragma unroll
        for (int ks = 0; ks < 2; ks++) {
            const int k0 = ks << 4;
            uint32_t ah[4][4], al[4][4], bb2[4][2];
#pragma unroll
            for (int i = 0; i < 4; i++) {
                const int ml = m0 + (i << 4) + ((qA & 1) << 3) + t8;
                const int kl = k0 + ((qA >> 1) << 3);
                uint32_t off = (uint32_t)((ml << 6) + (kl << 1));
                uint32_t swo = off ^ ((off >> 3) & 0x30);
                ldmx4(ah[i], sb + bofs + swo);
                ldmx4(al[i], sb + bofs + 8192u + swo);
            }
#pragma unroll
            for (int jp = 0; jp < 2; jp++) {
                const int nl = n0 + (jp << 4) + (jjB << 3) + t8;
                const int kl = k0 + (qbB << 3);
                uint32_t off = (uint32_t)((nl << 6) + (kl << 1));
                uint32_t swo = off ^ ((off >> 3) & 0x30);
                uint32_t tmp[4];
                ldmx4(tmp, sb + bofs + 16384u + swo);
                bb2[jp * 2][0] = tmp[0]; bb2[jp * 2][1] = tmp[1];
                bb2[jp * 2 + 1][0] = tmp[2]; bb2[jp * 2 + 1][1] = tmp[3];
            }
#pragma unroll
            for (int i = 0; i < 4; i++)
#pragma unroll
                for (int j = 0; j < 4; j++) {
                    mma16816(acc[i][j], ah[i], bb2[j]);
                    mma16816(acc[i][j], al[i], bb2[j]);
                }
#pragma unroll
            for (int jp = 0; jp < 2; jp++) {
                const int nl = n0 + (jp << 4) + (jjB << 3) + t8;
                const int kl = k0 + (qbB << 3);
                uint32_t off = (uint32_t)((nl << 6) + (kl << 1));
                uint32_t swo = off ^ ((off >> 3) & 0x30);
                uint32_t tmp[4];
                ldmx4(tmp, sb + bofs + 24576u + swo);
                bb2[jp * 2][0] = tmp[0]; bb2[jp * 2][1] = tmp[1];
                bb2[jp * 2 + 1][0] = tmp[2]; bb2[jp * 2 + 1][1] = tmp[3];
            }
#pragma unroll
            for (int i = 0; i < 4; i++)
#pragma unroll
                for (int j = 0; j < 4; j++)
                    mma16816(acc[i][j], ah[i], bb2[j]);
        }
    }

    const int rA  = lane >> 2;
    const int cp2 = (lane & 3) << 1;
#pragma unroll
    for (int i = 0; i < 4; i++) {
#pragma unroll
        for (int j = 0; j < 4; j++) {
            const int col = col0 + n0 + (j << 3) + cp2;
            const float b0 = bias[col], b1 = bias[col + 1];
#pragma unroll
            for (int h = 0; h < 2; h++) {
                const int row = row0 + m0 + (i << 4) + rA + (h << 3);
                float vx = acc[i][j][h * 2 + 0] + b0;
                float vy = acc[i][j][h * 2 + 1] + b1;
                if (RESID) {
                    const float2 rv = *(const float2*)&resid[(size_t)row * N + col];
                    vx += rv.x; vy += rv.y;
                }
                if (RELU) { vx = fmaxf(vx, 0.f); vy = fmaxf(vy, 0.f); }
                if (SPLIT_OUT) {
                    __nv_bfloat16 hx, lx, hy, ly;
                    split_bf16(vx, hx, lx); split_bf16(vy, hy, ly);
                    const size_t o = (size_t)row * N + col;
                    *(__nv_bfloat162*)&Ch[o] = __nv_bfloat162(hx, hy);
                    *(__nv_bfloat162*)&Cl[o] = __nv_bfloat162(lx, ly);
                } else if (QKV_STORE) {
                    const int b_ = row >> 11, l_ = row & (SEQ - 1);
                    const int h_ = col >> 6, hd_ = col & 63;
                    *(float2*)&C[(((size_t)(b_ * NHEAD + h_) * SEQ) + l_) * HDIM + hd_] =
                        make_float2(vx, vy);
                } else {
                    *(float2*)&C[(size_t)row * N + col] = make_float2(vx, vy);
                }
            }
        }
    }
}

/* ================= Flash attention: register-prefetched K/V/bias ===== */
#define FL_SMEM_FLOATS (3 * 64 * 65 + 64 * 64)
#define FL_SMEM_BYTES  (FL_SMEM_FLOATS * 4)

__global__ __launch_bounds__(256)
void flash_kernel(const float* __restrict__ Qg, const float* __restrict__ Kg,
                  const float* __restrict__ Vg, const float* __restrict__ Bg,
                  __nv_bfloat16* __restrict__ Oh, __nv_bfloat16* __restrict__ Ol)
{
    extern __shared__ float fsm[];
    float (*Qs)[65] = (float(*)[65]) fsm;
    float (*Ks)[65] = (float(*)[65])(fsm + 64 * 65);
    float (*Ps)[65] = (float(*)[65])(fsm + 2 * 64 * 65);
    float (*Vs)[64] = (float(*)[64])(fsm + 3 * 64 * 65);

    const int tid = threadIdx.x;
    const int tx  = tid & 15, ty = tid >> 4;
    const int bh  = blockIdx.y;
    const int h   = bh & (NHEAD - 1);
    const int b   = bh >> 4;
    const int qt  = gridDim.x - 1 - blockIdx.x;
    const int q0  = qt << 6;

    const float* Qp = Qg + ((size_t)bh * SEQ + q0) * HDIM;
    const float* Kp = Kg + (size_t)bh * SEQ * HDIM;
    const float* Vp = Vg + (size_t)bh * SEQ * HDIM;
    const float* Bp = Bg + (size_t)h * SEQ * SEQ;

    const int pr = tid >> 4, ps = (tid & 15) << 2;   /* prefetch mapping */

    for (int i = tid; i < 1024; i += 256) {
        const int r = i >> 4, s = (i & 15) << 2;
        float4 qv = *(const float4*)(Qp + r * HDIM + s);
        Qs[r][s] = qv.x; Qs[r][s + 1] = qv.y; Qs[r][s + 2] = qv.z; Qs[r][s + 3] = qv.w;
    }

    float m_i[4], l_i[4], oacc[4][4];
#pragma unroll
    for (int i = 0; i < 4; i++) {
        m_i[i] = -1e30f; l_i[i] = 0.f;
#pragma unroll
        for (int j = 0; j < 4; j++) oacc[i][j] = 0.f;
    }

    const float scale = 0.125f;
    const int ntiles = qt + 1;

    /* prefetch tile 0 K/V into registers */
    float4 kpre[4], vpre[4];
#pragma unroll
    for (int it = 0; it < 4; it++) {
        const int r = pr + (it << 4);
        kpre[it] = *(const float4*)(Kp + (size_t)r * HDIM + ps);
        vpre[it] = *(const float4*)(Vp + (size_t)r * HDIM + ps);
    }

    for (int kt = 0; kt < ntiles; kt++) {
        const int k0 = kt << 6;
        __syncthreads();
        /* store prefetched K/V tile */
#pragma unroll
        for (int it = 0; it < 4; it++) {
            const int r = pr + (it << 4);
            Ks[r][ps] = kpre[it].x; Ks[r][ps + 1] = kpre[it].y;
            Ks[r][ps + 2] = kpre[it].z; Ks[r][ps + 3] = kpre[it].w;
            *(float4*)&Vs[r][ps] = vpre[it];
        }
        /* issue next tile's K/V loads (hidden under S/softmax/PV compute) */
        if (kt + 1 < ntiles) {
            const int k1 = k0 + 64;
#pragma unroll
            for (int it = 0; it < 4; it++) {
                const int r = k1 + pr + (it << 4);
                kpre[it] = *(const float4*)(Kp + (size_t)r * HDIM + ps);
                vpre[it] = *(const float4*)(Vp + (size_t)r * HDIM + ps);
            }
        }
        /* issue this tile's bias loads (consumed after S compute) */
        float4 bvv[4];
#pragma unroll
        for (int i = 0; i < 4; i++)
            bvv[i] = *(const float4*)(Bp + (size_t)(q0 + (ty << 2) + i) * SEQ + k0 + (tx << 2));
        __syncthreads();

        float sv[4][4];
#pragma unroll
        for (int i = 0; i < 4; i++)
#pragma unroll
            for (int j = 0; j < 4; j++) sv[i][j] = 0.f;
#pragma unroll 8
        for (int d = 0; d < 64; d++) {
            float qf[4], kf[4];
#pragma unroll
            for (int i = 0; i < 4; i++) qf[i] = Qs[(ty << 2) + i][d];
#pragma unroll
            for (int j = 0; j < 4; j++) kf[j] = Ks[(tx << 2) + j][d];
#pragma unroll
            for (int i = 0; i < 4; i++)
#pragma unroll
                for (int j = 0; j < 4; j++)
                    sv[i][j] = fmaf(qf[i], kf[j], sv[i][j]);
        }

#pragma unroll
        for (int i = 0; i < 4; i++) {
            const int qi = q0 + (ty << 2) + i;
            float bb[4] = {bvv[i].x, bvv[i].y, bvv[i].z, bvv[i].w};
#pragma unroll
            for (int j = 0; j < 4; j++) {
                const int kj = k0 + (tx << 2) + j;
                sv[i][j] = (kj <= qi) ? fmaf(sv[i][j], scale, bb[j]) : -1e30f;
            }
        }

#pragma unroll
        for (int i = 0; i < 4; i++) {
            float rmax = fmaxf(fmaxf(sv[i][0], sv[i][1]), fmaxf(sv[i][2], sv[i][3]));
#pragma unroll
            for (int o = 8; o > 0; o >>= 1)
                rmax = fmaxf(rmax, __shfl_xor_sync(0xffffffffu, rmax, o, 16));
            const float mnew = fmaxf(m_i[i], rmax);
            const float corr = __expf(m_i[i] - mnew);
            float rsum = 0.f;
#pragma unroll
            for (int j = 0; j < 4; j++) {
                sv[i][j] = __expf(sv[i][j] - mnew);
                rsum += sv[i][j];
            }
#pragma unroll
            for (int o = 8; o > 0; o >>= 1)
                rsum += __shfl_xor_sync(0xffffffffu, rsum, o, 16);
            l_i[i] = l_i[i] * corr + rsum;
            m_i[i] = mnew;
#pragma unroll
            for (int j = 0; j < 4; j++) oacc[i][j] *= corr;
#pragma unroll
            for (int j = 0; j < 4; j++)
                Ps[(ty << 2) + i][(tx << 2) + j] = sv[i][j];
        }
        __syncthreads();

#pragma unroll 8
        for (int c = 0; c < 64; c++) {
            float pf[4];
#pragma unroll
            for (int i = 0; i < 4; i++) pf[i] = Ps[(ty << 2) + i][c];
            float4 vf = *(const float4*)&Vs[c][tx << 2];
#pragma unroll
            for (int i = 0; i < 4; i++) {
                oacc[i][0] = fmaf(pf[i], vf.x, oacc[i][0]);
                oacc[i][1] = fmaf(pf[i], vf.y, oacc[i][1]);
                oacc[i][2] = fmaf(pf[i], vf.z, oacc[i][2]);
                oacc[i][3] = fmaf(pf[i], vf.w, oacc[i][3]);
            }
        }
    }

#pragma unroll
    for (int i = 0; i < 4; i++) {
        const int qi = q0 + (ty << 2) + i;
        const float inv = 1.0f / l_i[i];
        float o0 = oacc[i][0] * inv, o1 = oacc[i][1] * inv;
        float o2 = oacc[i][2] * inv, o3 = oacc[i][3] * inv;
        __nv_bfloat16 h0, l0, h1, l1, h2, l2, h3, l3;
        split_bf16(o0, h0, l0); split_bf16(o1, h1, l1);
        split_bf16(o2, h2, l2); split_bf16(o3, h3, l3);
        const size_t o = ((size_t)b * SEQ + qi) * D_MODEL + h * HDIM + (tx << 2);
        *(__nv_bfloat162*)&Oh[o]     = __nv_bfloat162(h0, h1);
        *(__nv_bfloat162*)&Oh[o + 2] = __nv_bfloat162(h2, h3);
        *(__nv_bfloat162*)&Ol[o]     = __nv_bfloat162(l0, l1);
        *(__nv_bfloat162*)&Ol[o + 2] = __nv_bfloat162(l2, l3);
    }
}

/* ================= Host launcher ================= */
extern "C" void kernel_launch(void* const* d_in, const int* in_sizes, int n_in,
                              void* d_out, int out_size)
{
    (void)in_sizes; (void)n_in; (void)out_size;
    const float* x    = (const float*)d_in[0];
    const float* relb = (const float*)d_in[1];
    const float* wq   = (const float*)d_in[2];
    const float* bq   = (const float*)d_in[3];
    const float* wk   = (const float*)d_in[4];
    const float* bk   = (const float*)d_in[5];
    const float* wv   = (const float*)d_in[6];
    const float* bv   = (const float*)d_in[7];
    const float* wo   = (const float*)d_in[8];
    const float* bo   = (const float*)d_in[9];
    const float* g1   = (const float*)d_in[10];
    const float* be1  = (const float*)d_in[11];
    const float* g2   = (const float*)d_in[12];
    const float* be2  = (const float*)d_in[13];
    const float* w1   = (const float*)d_in[14];
    const float* bf1  = (const float*)d_in[15];
    const float* w2   = (const float*)d_in[16];
    const float* bf2  = (const float*)d_in[17];
    float* out = (float*)d_out;

    float *q, *k, *v, *x1;
    cudaGetSymbolAddress((void**)&q,  g_q);
    cudaGetSymbolAddress((void**)&k,  g_k);
    cudaGetSymbolAddress((void**)&v,  g_v);
    cudaGetSymbolAddress((void**)&x1, g_x1);

    __nv_bfloat16 *xnh, *xnl, *ath, *atl, *hh, *hl;
    cudaGetSymbolAddress((void**)&xnh, g_xn_h);   cudaGetSymbolAddress((void**)&xnl, g_xn_l);
    cudaGetSymbolAddress((void**)&ath, g_attn_h); cudaGetSymbolAddress((void**)&atl, g_attn_l);
    cudaGetSymbolAddress((void**)&hh,  g_h_h);    cudaGetSymbolAddress((void**)&hl,  g_h_l);

    __nv_bfloat16 *wqh, *wql, *wkh, *wkl, *wvh, *wvl, *woh, *wol, *w1h, *w1l, *w2h, *w2l;
    cudaGetSymbolAddress((void**)&wqh, g_wq_h); cudaGetSymbolAddress((void**)&wql, g_wq_l);
    cudaGetSymbolAddress((void**)&wkh, g_wk_h); cudaGetSymbolAddress((void**)&wkl, g_wk_l);
    cudaGetSymbolAddress((void**)&wvh, g_wv_h); cudaGetSymbolAddress((void**)&wvl, g_wv_l);
    cudaGetSymbolAddress((void**)&woh, g_wo_h); cudaGetSymbolAddress((void**)&wol, g_wo_l);
    cudaGetSymbolAddress((void**)&w1h, g_w1_h); cudaGetSymbolAddress((void**)&w1l, g_w1_l);
    cudaGetSymbolAddress((void**)&w2h, g_w2_h); cudaGetSymbolAddress((void**)&w2l, g_w2_l);

    cudaFuncSetAttribute(flash_kernel,
                         cudaFuncAttributeMaxDynamicSharedMemorySize, FL_SMEM_BYTES);
    cudaFuncSetAttribute(tgemm_kernel<true,  false, false, false>,
                         cudaFuncAttributeMaxDynamicSharedMemorySize, G_SMEM_BYTES);
    cudaFuncSetAttribute(tgemm_kernel<false, false, true,  false>,
                         cudaFuncAttributeMaxDynamicSharedMemorySize, G_SMEM_BYTES);
    cudaFuncSetAttribute(tgemm_kernel<false, true,  false, true>,
                         cudaFuncAttributeMaxDynamicSharedMemorySize, G_SMEM_BYTES);

    const dim3 wb(32, 8);
    const dim3 gd1024(D_MODEL / 128, ROWS / 128);  /* (8, 64)  */
    const dim3 gd4096(FFN_DIM / 128, ROWS / 128);  /* (32, 64) */

    /* launch order arranged so ncu (-s 5 -c 1) profiles a GEMM (launch #5) */
    wprep_kernel<<<dim3(D_MODEL / 32, D_MODEL / 32), wb>>>(wq, wqh, wql, D_MODEL, D_MODEL);  /* 0 */
    wprep_kernel<<<dim3(D_MODEL / 32, D_MODEL / 32), wb>>>(wk, wkh, wkl, D_MODEL, D_MODEL);  /* 1 */
    wprep_kernel<<<dim3(D_MODEL / 32, D_MODEL / 32), wb>>>(wv, wvh, wvl, D_MODEL, D_MODEL);  /* 2 */
    ln_kernel<<<ROWS, 256>>>(x, g1, be1, xnh, xnl);                                          /* 3 */
    tgemm_kernel<true,  false, false, false><<<gd1024, 256, G_SMEM_BYTES>>>(
        xnh, xnl, wqh, wql, bq, nullptr, q, nullptr, nullptr, D_MODEL, D_MODEL);             /* 4 */
    tgemm_kernel<true,  false, false, false><<<gd1024, 256, G_SMEM_BYTES>>>(
        xnh, xnl, wkh, wkl, bk, nullptr, k, nullptr, nullptr, D_MODEL, D_MODEL);             /* 5: PROFILED */
    tgemm_kernel<true,  false, false, false><<<gd1024, 256, G_SMEM_BYTES>>>(
        xnh, xnl, wvh, wvl, bv, nullptr, v, nullptr, nullptr, D_MODEL, D_MODEL);             /* 6 */
    wprep_kernel<<<dim3(D_MODEL / 32, D_MODEL / 32), wb>>>(wo, woh, wol, D_MODEL, D_MODEL);  /* 7 */
    wprep_kernel<<<dim3(FFN_DIM / 32, D_MODEL / 32), wb>>>(w1, w1h, w1l, D_MODEL, FFN_DIM);  /* 8 */
    wprep_kernel<<<dim3(D_MODEL / 32, FFN_DIM / 32), wb>>>(w2, w2h, w2l, FFN_DIM, D_MODEL);  /* 9 */
    flash_kernel<<<dim3(SEQ / 64, BATCH * NHEAD), 256, FL_SMEM_BYTES>>>(q, k, v, relb, ath, atl);
    tgemm_kernel<false, false, true,  false><<<gd1024, 256, G_SMEM_BYTES>>>(
        ath, atl, woh, wol, bo, x, x1, nullptr, nullptr, D_MODEL, D_MODEL);
    ln_kernel<<<ROWS, 256>>>(x1, g2, be2, xnh, xnl);
    tgemm_kernel<false, true,  false, true ><<<gd4096, 256, G_SMEM_BYTES>>>(
        xnh, xnl, w1h, w1l, bf1, nullptr, nullptr, hh, hl, FFN_DIM, D_MODEL);
    tgemm_kernel<false, false, true,  false><<<gd1024, 256, G_SMEM_BYTES>>>(
        hh, hl, w2h, w2l, bf2, x1, out, nullptr, nullptr, D_MODEL, FFN_DIM);
}